// round 4
// baseline (speedup 1.0000x reference)
#include <cuda_runtime.h>

#define MR 65536
#define BR 2048
#define DIN 13
#define N1 300
#define N2 600
#define N3 100

// ---- scratch (device globals; no allocations anywhere) ----------------------
__device__ __align__(16) float g_H1[(size_t)MR * N1];
__device__ __align__(16) float g_H2[(size_t)MR * N2];
__device__ __align__(16) float g_H3[(size_t)MR * N3];
__device__ __align__(16) float g_T1s[(size_t)MR * 16];  // normalized t1 * 23, padded
__device__ __align__(16) float g_T2n[BR * 16];          // normalized value, padded
__device__ unsigned int g_keys[BR];

// ---- f32x2 packed FMA helpers ----------------------------------------------
__device__ __forceinline__ unsigned long long pack_dup(float a) {
    unsigned long long r; asm("mov.b64 %0, {%1, %1};" : "=l"(r) : "f"(a)); return r;
}
__device__ __forceinline__ unsigned long long pack2(float x, float y) {
    unsigned long long r; asm("mov.b64 %0, {%1, %2};" : "=l"(r) : "f"(x), "f"(y)); return r;
}
__device__ __forceinline__ float2 unpack2(unsigned long long v) {
    float2 f; asm("mov.b64 {%0, %1}, %2;" : "=f"(f.x), "=f"(f.y) : "l"(v)); return f;
}
__device__ __forceinline__ void ffma2(unsigned long long& d, unsigned long long a,
                                      unsigned long long b) {
    asm("fma.rn.f32x2 %0, %1, %2, %0;" : "+l"(d) : "l"(a), "l"(b));
}
__device__ __forceinline__ unsigned int fkey(float f) {
    unsigned int u = __float_as_uint(f);
    return ((int)u < 0) ? ~u : (u | 0x80000000u);
}

// ---- K1: H1 = relu(memory @ W1^T + b1), warp per row ------------------------
__global__ void __launch_bounds__(256)
k1_layer1(const float* __restrict__ mem, const float* __restrict__ W1,
          const float* __restrict__ b1) {
    __shared__ float w1s[N1 * 17];
    __shared__ float b1s[N1];
    int tid = threadIdx.x;
    for (int idx = tid; idx < N1 * DIN; idx += 256)
        w1s[(idx / DIN) * 17 + (idx % DIN)] = W1[idx];
    for (int idx = tid; idx < N1; idx += 256) b1s[idx] = b1[idx];
    __syncthreads();
    int warp = tid >> 5, lane = tid & 31;
    int row = blockIdx.x * 8 + warp;
    const float* xr = mem + (size_t)row * DIN;
    float x[DIN];
#pragma unroll
    for (int k = 0; k < DIN; k++) x[k] = __ldg(xr + k);
    float* orow = g_H1 + (size_t)row * N1;
#pragma unroll
    for (int j = 0; j < 10; j++) {
        int o = lane + 32 * j;
        if (o < N1) {
            float acc = b1s[o];
            const float* w = &w1s[o * 17];
#pragma unroll
            for (int k = 0; k < DIN; k++) acc = fmaf(x[k], w[k], acc);
            orow[o] = fmaxf(acc, 0.0f);
        }
    }
}

// ---- register-tiled fp32 GEMM + activation ---------------------------------
// C[M,NOUT] = act(A[M,K] @ W[NOUT,K]^T + bias), CTA 128x128, 256 thr,
// micro-tile 4 rows x 16 cols as strided pairs (col = tc*2 + 16*p) -> B-tile
// LDS.64 reads hit 16 consecutive banks, conflict-free.
template <int K, int KC, int NOUT, bool LEAKY, int STAGE>
__global__ void __launch_bounds__(256)
gemm_act(const float* __restrict__ W, const float* __restrict__ bias) {
    const float* __restrict__ A = (STAGE == 2) ? g_H1 : g_H2;
    float* __restrict__ C = (STAGE == 2) ? g_H2 : g_H3;
    constexpr int KCP = KC + 1;
    constexpr int BNP = 132;
    constexpr int NC = K / KC;
    constexpr int HKC = KC / 2;
    constexpr int LPT = 128 * HKC / 256;

    __shared__ __align__(16) float As[128 * KCP];
    __shared__ __align__(16) float Bs[KC * BNP];

    int tid = threadIdx.x;
    int rowBase = blockIdx.x * 128;
    int colBase = blockIdx.y * 128;
    int tr = tid >> 3, tc = tid & 7;
    int r0 = tr * 4;

    unsigned long long acc[4][8];
    {
#pragma unroll
        for (int p = 0; p < 8; p++) {
            int c = colBase + tc * 2 + 16 * p;
            float bx = (c < NOUT) ? __ldg(bias + c) : 0.0f;
            float by = (c + 1 < NOUT) ? __ldg(bias + c + 1) : 0.0f;
            unsigned long long bi = pack2(bx, by);
            acc[0][p] = bi; acc[1][p] = bi; acc[2][p] = bi; acc[3][p] = bi;
        }
    }

    float2 aR[LPT], bR[LPT];
    auto loadChunk = [&](int c) {
#pragma unroll
        for (int l = 0; l < LPT; l++) {
            int idx = tid + l * 256;
            int r = idx / HKC, q = idx - r * HKC;
            aR[l] = *(const float2*)(A + (size_t)(rowBase + r) * K + c * KC + 2 * q);
            int n = colBase + r;
            bR[l] = (n < NOUT) ? *(const float2*)(W + (size_t)n * K + c * KC + 2 * q)
                               : make_float2(0.0f, 0.0f);
        }
    };

    loadChunk(0);
    for (int c = 0; c < NC; c++) {
#pragma unroll
        for (int l = 0; l < LPT; l++) {
            int idx = tid + l * 256;
            int r = idx / HKC, q = idx - r * HKC;
            As[r * KCP + 2 * q] = aR[l].x;
            As[r * KCP + 2 * q + 1] = aR[l].y;
            Bs[(2 * q) * BNP + r] = bR[l].x;
            Bs[(2 * q + 1) * BNP + r] = bR[l].y;
        }
        __syncthreads();
        if (c + 1 < NC) loadChunk(c + 1);

#pragma unroll
        for (int kk = 0; kk < KC; kk++) {
            unsigned long long ap0 = pack_dup(As[(r0 + 0) * KCP + kk]);
            unsigned long long ap1 = pack_dup(As[(r0 + 1) * KCP + kk]);
            unsigned long long ap2 = pack_dup(As[(r0 + 2) * KCP + kk]);
            unsigned long long ap3 = pack_dup(As[(r0 + 3) * KCP + kk]);
            const float* brow = &Bs[kk * BNP];
#pragma unroll
            for (int p = 0; p < 8; p++) {
                unsigned long long bp =
                    *(const unsigned long long*)(brow + tc * 2 + 16 * p);
                ffma2(acc[0][p], ap0, bp);
                ffma2(acc[1][p], ap1, bp);
                ffma2(acc[2][p], ap2, bp);
                ffma2(acc[3][p], ap3, bp);
            }
        }
        __syncthreads();
    }

#pragma unroll
    for (int i = 0; i < 4; i++) {
        int row = rowBase + r0 + i;
#pragma unroll
        for (int p = 0; p < 8; p++) {
            int col = colBase + tc * 2 + 16 * p;
            if (col < NOUT) {
                float2 v = unpack2(acc[i][p]);
                if (LEAKY) {
                    v.x = v.x > 0.f ? v.x : 0.01f * v.x;
                    v.y = v.y > 0.f ? v.y : 0.01f * v.y;
                } else {
                    v.x = fmaxf(v.x, 0.f);
                    v.y = fmaxf(v.y, 0.f);
                }
                *(float2*)(C + (size_t)row * NOUT + col) = v;
            }
        }
    }
}

// ---- K4: t1 = leaky(H3 @ W4^T + b4); T1s = t1 * 23 / max(||t1||,eps) --------
__global__ void __launch_bounds__(256)
k4_layer4(const float* __restrict__ W4, const float* __restrict__ b4) {
    __shared__ float w4s[16 * 101];
    __shared__ float b4s[16];
    int tid = threadIdx.x;
    for (int idx = tid; idx < 16 * 101; idx += 256) w4s[idx] = 0.0f;
    __syncthreads();
    for (int idx = tid; idx < DIN * N3; idx += 256) {
        int o = idx / N3, k = idx - o * N3;
        w4s[o * 101 + k] = W4[idx];
    }
    if (tid < 16) b4s[tid] = (tid < DIN) ? b4[tid] : 0.0f;
    __syncthreads();

    int half = tid >> 4, o = tid & 15;
    int row = blockIdx.x * 16 + half;
    const float* h = g_H3 + (size_t)row * N3;
    const float* w = &w4s[o * 101];
    float acc = b4s[o];
#pragma unroll
    for (int j = 0; j < 25; j++) {
        float4 hv = *(const float4*)(h + 4 * j);
        acc = fmaf(hv.x, w[4 * j + 0], acc);
        acc = fmaf(hv.y, w[4 * j + 1], acc);
        acc = fmaf(hv.z, w[4 * j + 2], acc);
        acc = fmaf(hv.w, w[4 * j + 3], acc);
    }
    float t = acc > 0.0f ? acc : 0.01f * acc;
    float ss = t * t;
#pragma unroll
    for (int off = 8; off > 0; off >>= 1)
        ss += __shfl_xor_sync(0xffffffffu, ss, off, 16);
    float scale = 23.0f / fmaxf(sqrtf(ss), 1e-8f);
    g_T1s[(size_t)row * 16 + o] = t * scale;
}

// ---- K0: normalize value rows; init keys ------------------------------------
__global__ void k0_t2norm(const float* __restrict__ value) {
    int b = blockIdx.x * 256 + threadIdx.x;
    if (b >= BR) return;
    float t[DIN], ss = 0.0f;
#pragma unroll
    for (int k = 0; k < DIN; k++) {
        t[k] = value[b * DIN + k];
        ss = fmaf(t[k], t[k], ss);
    }
    float s = 1.0f / fmaxf(sqrtf(ss), 1e-8f);
#pragma unroll
    for (int k = 0; k < DIN; k++) g_T2n[b * 16 + k] = t[k] * s;
    g_T2n[b * 16 + 13] = 0.0f;
    g_T2n[b * 16 + 14] = 0.0f;
    g_T2n[b * 16 + 15] = 0.0f;
    g_keys[b] = 0u;
}

// ---- K5: similarity + running max ------------------------------------------
// grid (MR/128, BR/512). t2 tile 512x16 + t1 tile 128x16 in smem; each thread
// owns 2 b-rows in regs, scans the m-tile with f32x2 dots, atomicMax of key.
__global__ void __launch_bounds__(256)
k5_simmax() {
    __shared__ __align__(16) float t2s[512 * 16];
    __shared__ __align__(16) float t1s[128 * 16];
    int tid = threadIdx.x;
    int mBase = blockIdx.x * 128;
    int bBase = blockIdx.y * 512;

    const float4* s2 = (const float4*)(g_T2n + (size_t)bBase * 16);
    float4* d2 = (float4*)t2s;
#pragma unroll
    for (int l = 0; l < 8; l++) d2[tid + l * 256] = s2[tid + l * 256];
    const float4* s1 = (const float4*)(g_T1s + (size_t)mBase * 16);
    float4* d1 = (float4*)t1s;
#pragma unroll
    for (int l = 0; l < 2; l++) d1[tid + l * 256] = s1[tid + l * 256];
    __syncthreads();

    unsigned long long v0[8], v1[8];
#pragma unroll
    for (int p = 0; p < 8; p++) {
        v0[p] = *(const unsigned long long*)(t2s + tid * 16 + 2 * p);
        v1[p] = *(const unsigned long long*)(t2s + (tid + 256) * 16 + 2 * p);
    }
    float m0 = -3.4e38f, m1 = -3.4e38f;
    for (int m = 0; m < 128; m++) {
        const float* u = &t1s[m * 16];
        unsigned long long a0 = 0, a1 = 0;
#pragma unroll
        for (int p = 0; p < 8; p++) {
            unsigned long long up = *(const unsigned long long*)(u + 2 * p);
            ffma2(a0, v0[p], up);
            ffma2(a1, v1[p], up);
        }
        float2 f0 = unpack2(a0), f1 = unpack2(a1);
        m0 = fmaxf(m0, f0.x + f0.y);
        m1 = fmaxf(m1, f1.x + f1.y);
    }
    atomicMax(&g_keys[bBase + tid], fkey(m0));
    atomicMax(&g_keys[bBase + tid + 256], fkey(m1));
}

// ---- K6: decode keys -> fp32 output ----------------------------------------
__global__ void k6_decode(float* __restrict__ out) {
    int b = blockIdx.x * 256 + threadIdx.x;
    if (b >= BR) return;
    unsigned int k = g_keys[b];
    unsigned int u = (k & 0x80000000u) ? (k ^ 0x80000000u) : ~k;
    out[b] = __uint_as_float(u);
}

// ---- launch -----------------------------------------------------------------
extern "C" void kernel_launch(void* const* d_in, const int* in_sizes, int n_in,
                              void* d_out, int out_size) {
    const float* mem = (const float*)d_in[0];
    const float* value = (const float*)d_in[1];
    const float* W1 = (const float*)d_in[2];
    const float* b1 = (const float*)d_in[3];
    const float* W2 = (const float*)d_in[4];
    const float* b2 = (const float*)d_in[5];
    const float* W3 = (const float*)d_in[6];
    const float* b3 = (const float*)d_in[7];
    const float* W4 = (const float*)d_in[8];
    const float* b4 = (const float*)d_in[9];
    float* out = (float*)d_out;

    k0_t2norm<<<BR / 256, 256>>>(value);
    k1_layer1<<<MR / 8, 256>>>(mem, W1, b1);
    gemm_act<300, 20, 600, true, 2><<<dim3(MR / 128, 5), 256>>>(W2, b2);
    gemm_act<600, 24, 100, false, 3><<<dim3(MR / 128, 1), 256>>>(W3, b3);
    k4_layer4<<<MR / 16, 256>>>(W4, b4);
    k5_simmax<<<dim3(MR / 128, BR / 512), 256>>>();
    k6_decode<<<BR / 256, 256>>>(out);
}

// round 6
// speedup vs baseline: 1.0849x; 1.0849x over previous
#include <cuda_runtime.h>

#define MR 65536
#define BR 2048
#define DIN 13
#define N1 300
#define N2 600
#define N3 100

// ---- scratch (device globals; no allocations anywhere) ----------------------
__device__ __align__(16) float g_H1[(size_t)MR * N1];
__device__ __align__(16) float g_H2[(size_t)MR * N2];
__device__ __align__(16) float g_H3[(size_t)MR * N3];
__device__ __align__(16) float g_T1s[(size_t)MR * 16];  // normalized t1 * 23, padded
__device__ __align__(16) float g_T2n[BR * 16];          // normalized value, padded
__device__ unsigned int g_keys[BR];

// ---- f32x2 packed FMA helpers ----------------------------------------------
__device__ __forceinline__ unsigned long long pack_dup(float a) {
    unsigned long long r; asm("mov.b64 %0, {%1, %1};" : "=l"(r) : "f"(a)); return r;
}
__device__ __forceinline__ unsigned long long pack2(float x, float y) {
    unsigned long long r; asm("mov.b64 %0, {%1, %2};" : "=l"(r) : "f"(x), "f"(y)); return r;
}
__device__ __forceinline__ float2 unpack2(unsigned long long v) {
    float2 f; asm("mov.b64 {%0, %1}, %2;" : "=f"(f.x), "=f"(f.y) : "l"(v)); return f;
}
__device__ __forceinline__ void ffma2(unsigned long long& d, unsigned long long a,
                                      unsigned long long b) {
    asm("fma.rn.f32x2 %0, %1, %2, %0;" : "+l"(d) : "l"(a), "l"(b));
}
__device__ __forceinline__ unsigned int fkey(float f) {
    unsigned int u = __float_as_uint(f);
    return ((int)u < 0) ? ~u : (u | 0x80000000u);
}

// ---- K1: H1 = relu(memory @ W1^T + b1), warp per row ------------------------
__global__ void __launch_bounds__(256)
k1_layer1(const float* __restrict__ mem, const float* __restrict__ W1,
          const float* __restrict__ b1) {
    __shared__ float w1s[N1 * 17];
    __shared__ float b1s[N1];
    int tid = threadIdx.x;
    for (int idx = tid; idx < N1 * DIN; idx += 256)
        w1s[(idx / DIN) * 17 + (idx % DIN)] = W1[idx];
    for (int idx = tid; idx < N1; idx += 256) b1s[idx] = b1[idx];
    __syncthreads();
    int warp = tid >> 5, lane = tid & 31;
    int row = blockIdx.x * 8 + warp;
    const float* xr = mem + (size_t)row * DIN;
    float x[DIN];
#pragma unroll
    for (int k = 0; k < DIN; k++) x[k] = __ldg(xr + k);
    float* orow = g_H1 + (size_t)row * N1;
#pragma unroll
    for (int j = 0; j < 10; j++) {
        int o = lane + 32 * j;
        if (o < N1) {
            float acc = b1s[o];
            const float* w = &w1s[o * 17];
#pragma unroll
            for (int k = 0; k < DIN; k++) acc = fmaf(x[k], w[k], acc);
            orow[o] = fmaxf(acc, 0.0f);
        }
    }
}

// ---- register-tiled fp32 GEMM + activation ---------------------------------
// C[M,NOUT] = act(A[M,K] @ W[NOUT,K]^T + bias), CTA 128 x (16*NP), 256 thr,
// 2 CTAs/SM (launch_bounds). Micro-tile 4 rows x 2*NP cols as strided pairs
// (col = tc*2 + 16*p) -> conflict-free LDS.64 B reads with 4-way broadcast.
template <int K, int KC, int NOUT, int NP, bool LEAKY, int STAGE>
__global__ void __launch_bounds__(256, 2)
gemm_act(const float* __restrict__ W, const float* __restrict__ bias) {
    const float* __restrict__ A = (STAGE == 2) ? g_H1 : g_H2;
    float* __restrict__ C = (STAGE == 2) ? g_H2 : g_H3;
    constexpr int KCP = KC + 1;
    constexpr int BNP = 132;
    constexpr int NC = K / KC;
    constexpr int HKC = KC / 2;
    constexpr int LPT = 128 * HKC / 256;

    __shared__ __align__(16) float As[128 * KCP];
    __shared__ __align__(16) float Bs[KC * BNP];

    int tid = threadIdx.x;
    int rowBase = blockIdx.x * 128;
    int colBase = blockIdx.y * (16 * NP);
    int tr = tid >> 3, tc = tid & 7;
    int r0 = tr * 4;

    unsigned long long acc[4][NP];
    {
#pragma unroll
        for (int p = 0; p < NP; p++) {
            int c = colBase + tc * 2 + 16 * p;
            float bx = (c < NOUT) ? __ldg(bias + c) : 0.0f;
            float by = (c + 1 < NOUT) ? __ldg(bias + c + 1) : 0.0f;
            unsigned long long bi = pack2(bx, by);
            acc[0][p] = bi; acc[1][p] = bi; acc[2][p] = bi; acc[3][p] = bi;
        }
    }

    float2 aR[LPT], bR[LPT];
    auto loadChunk = [&](int c) {
#pragma unroll
        for (int l = 0; l < LPT; l++) {
            int idx = tid + l * 256;
            int r = idx / HKC, q = idx - r * HKC;
            aR[l] = *(const float2*)(A + (size_t)(rowBase + r) * K + c * KC + 2 * q);
            int n = colBase + r;
            bR[l] = (n < NOUT) ? *(const float2*)(W + (size_t)n * K + c * KC + 2 * q)
                               : make_float2(0.0f, 0.0f);
        }
    };

    loadChunk(0);
    for (int c = 0; c < NC; c++) {
#pragma unroll
        for (int l = 0; l < LPT; l++) {
            int idx = tid + l * 256;
            int r = idx / HKC, q = idx - r * HKC;
            As[r * KCP + 2 * q] = aR[l].x;
            As[r * KCP + 2 * q + 1] = aR[l].y;
            Bs[(2 * q) * BNP + r] = bR[l].x;
            Bs[(2 * q + 1) * BNP + r] = bR[l].y;
        }
        __syncthreads();
        if (c + 1 < NC) loadChunk(c + 1);

#pragma unroll
        for (int kk = 0; kk < KC; kk++) {
            unsigned long long ap0 = pack_dup(As[(r0 + 0) * KCP + kk]);
            unsigned long long ap1 = pack_dup(As[(r0 + 1) * KCP + kk]);
            unsigned long long ap2 = pack_dup(As[(r0 + 2) * KCP + kk]);
            unsigned long long ap3 = pack_dup(As[(r0 + 3) * KCP + kk]);
            const float* brow = &Bs[kk * BNP];
#pragma unroll
            for (int p = 0; p < NP; p++) {
                unsigned long long bp =
                    *(const unsigned long long*)(brow + tc * 2 + 16 * p);
                ffma2(acc[0][p], ap0, bp);
                ffma2(acc[1][p], ap1, bp);
                ffma2(acc[2][p], ap2, bp);
                ffma2(acc[3][p], ap3, bp);
            }
        }
        __syncthreads();
    }

#pragma unroll
    for (int i = 0; i < 4; i++) {
        int row = rowBase + r0 + i;
#pragma unroll
        for (int p = 0; p < NP; p++) {
            int col = colBase + tc * 2 + 16 * p;
            if (col < NOUT) {
                float2 v = unpack2(acc[i][p]);
                if (LEAKY) {
                    v.x = v.x > 0.f ? v.x : 0.01f * v.x;
                    v.y = v.y > 0.f ? v.y : 0.01f * v.y;
                } else {
                    v.x = fmaxf(v.x, 0.f);
                    v.y = fmaxf(v.y, 0.f);
                }
                *(float2*)(C + (size_t)row * NOUT + col) = v;
            }
        }
    }
}

// ---- K4: t1 = leaky(H3 @ W4^T + b4); T1s = t1 * 23 / max(||t1||,eps) --------
__global__ void __launch_bounds__(256)
k4_layer4(const float* __restrict__ W4, const float* __restrict__ b4) {
    __shared__ float w4s[16 * 101];
    __shared__ float b4s[16];
    int tid = threadIdx.x;
    for (int idx = tid; idx < 16 * 101; idx += 256) w4s[idx] = 0.0f;
    __syncthreads();
    for (int idx = tid; idx < DIN * N3; idx += 256) {
        int o = idx / N3, k = idx - o * N3;
        w4s[o * 101 + k] = W4[idx];
    }
    if (tid < 16) b4s[tid] = (tid < DIN) ? b4[tid] : 0.0f;
    __syncthreads();

    int half = tid >> 4, o = tid & 15;
    int row = blockIdx.x * 16 + half;
    const float* h = g_H3 + (size_t)row * N3;
    const float* w = &w4s[o * 101];
    float acc = b4s[o];
#pragma unroll
    for (int j = 0; j < 25; j++) {
        float4 hv = *(const float4*)(h + 4 * j);
        acc = fmaf(hv.x, w[4 * j + 0], acc);
        acc = fmaf(hv.y, w[4 * j + 1], acc);
        acc = fmaf(hv.z, w[4 * j + 2], acc);
        acc = fmaf(hv.w, w[4 * j + 3], acc);
    }
    float t = acc > 0.0f ? acc : 0.01f * acc;
    float ss = t * t;
#pragma unroll
    for (int off = 8; off > 0; off >>= 1)
        ss += __shfl_xor_sync(0xffffffffu, ss, off, 16);
    float scale = 23.0f / fmaxf(sqrtf(ss), 1e-8f);
    g_T1s[(size_t)row * 16 + o] = t * scale;
}

// ---- K0: normalize value rows; init keys ------------------------------------
__global__ void k0_t2norm(const float* __restrict__ value) {
    int b = blockIdx.x * 256 + threadIdx.x;
    if (b >= BR) return;
    float t[DIN], ss = 0.0f;
#pragma unroll
    for (int k = 0; k < DIN; k++) {
        t[k] = value[b * DIN + k];
        ss = fmaf(t[k], t[k], ss);
    }
    float s = 1.0f / fmaxf(sqrtf(ss), 1e-8f);
#pragma unroll
    for (int k = 0; k < DIN; k++) g_T2n[b * 16 + k] = t[k] * s;
    g_T2n[b * 16 + 13] = 0.0f;
    g_T2n[b * 16 + 14] = 0.0f;
    g_T2n[b * 16 + 15] = 0.0f;
    g_keys[b] = 0u;
}

// ---- K5: similarity + running max ------------------------------------------
// grid (MR/128, BR/512). t2 tile 512x16 + t1 tile 128x16 in smem; each thread
// owns 2 b-rows in regs, scans the m-tile with f32x2 dots, atomicMax of key.
__global__ void __launch_bounds__(256)
k5_simmax() {
    __shared__ __align__(16) float t2s[512 * 16];
    __shared__ __align__(16) float t1s[128 * 16];
    int tid = threadIdx.x;
    int mBase = blockIdx.x * 128;
    int bBase = blockIdx.y * 512;

    const float4* s2 = (const float4*)(g_T2n + (size_t)bBase * 16);
    float4* d2 = (float4*)t2s;
#pragma unroll
    for (int l = 0; l < 8; l++) d2[tid + l * 256] = s2[tid + l * 256];
    const float4* s1 = (const float4*)(g_T1s + (size_t)mBase * 16);
    float4* d1 = (float4*)t1s;
#pragma unroll
    for (int l = 0; l < 2; l++) d1[tid + l * 256] = s1[tid + l * 256];
    __syncthreads();

    unsigned long long v0[8], v1[8];
#pragma unroll
    for (int p = 0; p < 8; p++) {
        v0[p] = *(const unsigned long long*)(t2s + tid * 16 + 2 * p);
        v1[p] = *(const unsigned long long*)(t2s + (tid + 256) * 16 + 2 * p);
    }
    float m0 = -3.4e38f, m1 = -3.4e38f;
    for (int m = 0; m < 128; m++) {
        const float* u = &t1s[m * 16];
        unsigned long long a0 = 0, a1 = 0;
#pragma unroll
        for (int p = 0; p < 8; p++) {
            unsigned long long up = *(const unsigned long long*)(u + 2 * p);
            ffma2(a0, v0[p], up);
            ffma2(a1, v1[p], up);
        }
        float2 f0 = unpack2(a0), f1 = unpack2(a1);
        m0 = fmaxf(m0, f0.x + f0.y);
        m1 = fmaxf(m1, f1.x + f1.y);
    }
    atomicMax(&g_keys[bBase + tid], fkey(m0));
    atomicMax(&g_keys[bBase + tid + 256], fkey(m1));
}

// ---- K6: decode keys -> fp32 output ----------------------------------------
__global__ void k6_decode(float* __restrict__ out) {
    int b = blockIdx.x * 256 + threadIdx.x;
    if (b >= BR) return;
    unsigned int k = g_keys[b];
    unsigned int u = (k & 0x80000000u) ? (k ^ 0x80000000u) : ~k;
    out[b] = __uint_as_float(u);
}

// ---- launch -----------------------------------------------------------------
extern "C" void kernel_launch(void* const* d_in, const int* in_sizes, int n_in,
                              void* d_out, int out_size) {
    const float* mem = (const float*)d_in[0];
    const float* value = (const float*)d_in[1];
    const float* W1 = (const float*)d_in[2];
    const float* b1 = (const float*)d_in[3];
    const float* W2 = (const float*)d_in[4];
    const float* b2 = (const float*)d_in[5];
    const float* W3 = (const float*)d_in[6];
    const float* b3 = (const float*)d_in[7];
    const float* W4 = (const float*)d_in[8];
    const float* b4 = (const float*)d_in[9];
    float* out = (float*)d_out;

    k0_t2norm<<<BR / 256, 256>>>(value);
    k1_layer1<<<MR / 8, 256>>>(mem, W1, b1);
    gemm_act<300, 20, 600, 8, true, 2><<<dim3(MR / 128, 5), 256>>>(W2, b2);
    gemm_act<600, 24, 100, 7, false, 3><<<dim3(MR / 128, 1), 256>>>(W3, b3);
    k4_layer4<<<MR / 16, 256>>>(W4, b4);
    k5_simmax<<<dim3(MR / 128, BR / 512), 256>>>();
    k6_decode<<<BR / 256, 256>>>(out);
}